// round 1
// baseline (speedup 1.0000x reference)
#include <cuda_runtime.h>
#include <math.h>

#define HEADS 8
#define HD 32
#define NPOS 2304
#define GW 48
#define CDIM 256
#define BATCH 2
#define MTOT (BATCH*NPOS)   // 4608

// Scratch (static device arrays; no allocation allowed)
__device__ float g_q[BATCH*HEADS*NPOS*HD];     // [b][h][n][d] rotary-applied q
__device__ float g_k[BATCH*HEADS*NPOS*HD];     // [b][h][n][d] rotary-applied, scaled k
__device__ float g_v[BATCH*HEADS*NPOS*HD];     // [b][h][n][d] v
__device__ float g_lepe[BATCH*NPOS*CDIM];      // [b][n][c] depthwise conv out + bias
__device__ float g_attn[BATCH*NPOS*CDIM];      // [b][n][c] attention out (heads concat)
__device__ float g_wt[25*CDIM];                // transposed depthwise weights [tap][ch]

// ---------------------------------------------------------------------------
// Fused QKV GEMM: y = x @ W + b, with per-matrix epilogue
//   which=0: q -> rotary -> g_q
//   which=1: k -> *scale -> rotary -> g_k
//   which=2: v -> g_v
// Tiles: BM=BN=64, BK=16, 256 threads, 4x4 micro-tile.
// ---------------------------------------------------------------------------
__global__ __launch_bounds__(256) void qkv_gemm(
    const float* __restrict__ x,
    const float* __restrict__ Wq, const float* __restrict__ bq,
    const float* __restrict__ Wk, const float* __restrict__ bk,
    const float* __restrict__ Wv, const float* __restrict__ bv)
{
    const int which = blockIdx.z;
    const float* __restrict__ W    = (which == 0) ? Wq : (which == 1 ? Wk : Wv);
    const float* __restrict__ bias = (which == 0) ? bq : (which == 1 ? bk : bv);

    __shared__ float As[16][64];
    __shared__ float Bs[16][64];

    const int tid = threadIdx.x;
    const int tx = tid & 15, ty = tid >> 4;
    const int mb = blockIdx.x * 64, nb = blockIdx.y * 64;

    float acc[4][4];
#pragma unroll
    for (int i = 0; i < 4; i++)
#pragma unroll
        for (int j = 0; j < 4; j++) acc[i][j] = 0.f;

    const int ar = tid >> 2, ac4 = (tid & 3) * 4;   // A loader
    const int br = tid >> 4, bc4 = (tid & 15) * 4;  // B loader

    for (int k0 = 0; k0 < CDIM; k0 += 16) {
        float4 a = *(const float4*)&x[(size_t)(mb + ar) * CDIM + k0 + ac4];
        As[ac4 + 0][ar] = a.x; As[ac4 + 1][ar] = a.y;
        As[ac4 + 2][ar] = a.z; As[ac4 + 3][ar] = a.w;
        *(float4*)&Bs[br][bc4] = *(const float4*)&W[(size_t)(k0 + br) * CDIM + nb + bc4];
        __syncthreads();
#pragma unroll
        for (int kk = 0; kk < 16; kk++) {
            float4 av = *(float4*)&As[kk][ty * 4];
            float4 bv4 = *(float4*)&Bs[kk][tx * 4];
            acc[0][0] += av.x * bv4.x; acc[0][1] += av.x * bv4.y;
            acc[0][2] += av.x * bv4.z; acc[0][3] += av.x * bv4.w;
            acc[1][0] += av.y * bv4.x; acc[1][1] += av.y * bv4.y;
            acc[1][2] += av.y * bv4.z; acc[1][3] += av.y * bv4.w;
            acc[2][0] += av.z * bv4.x; acc[2][1] += av.z * bv4.y;
            acc[2][2] += av.z * bv4.z; acc[2][3] += av.z * bv4.w;
            acc[3][0] += av.w * bv4.x; acc[3][1] += av.w * bv4.y;
            acc[3][2] += av.w * bv4.z; acc[3][3] += av.w * bv4.w;
        }
        __syncthreads();
    }

    const float scal = (which == 1) ? 0.17677669529663687f : 1.0f; // 32^-0.5

#pragma unroll
    for (int i = 0; i < 4; i++) {
        int row = mb + ty * 4 + i;
        int b = row / NPOS;
        int pos = row - b * NPOS;
        if (which == 2) {
#pragma unroll
            for (int j = 0; j < 4; j++) {
                int col = nb + tx * 4 + j;
                float val = acc[i][j] + bias[col];
                g_v[(((size_t)(b * HEADS + (col >> 5))) * NPOS + pos) * HD + (col & 31)] = val;
            }
        } else {
            float* dst = (which == 0) ? g_q : g_k;
#pragma unroll
            for (int jj = 0; jj < 4; jj += 2) {
                int col = nb + tx * 4 + jj;
                int d = col & 31;
                int pj = d >> 1;                      // pair index 0..15
                // angle = 10000^(-pj/15) = exp(-pj * ln(1e4)/15)
                float ang = expf(-(float)pj * (9.210340371976184f / 15.0f));
                float s, c;
                sincosf((float)pos * ang, &s, &c);
                float v0 = (acc[i][jj] + bias[col]) * scal;
                float v1 = (acc[i][jj + 1] + bias[col + 1]) * scal;
                size_t base = (((size_t)(b * HEADS + (col >> 5))) * NPOS + pos) * HD + d;
                dst[base]     = v0 * c - v1 * s;
                dst[base + 1] = v1 * c + v0 * s;
            }
        }
    }
}

// ---------------------------------------------------------------------------
// Transpose depthwise weights [C][25] -> [25][C] for coalesced conv loads
// ---------------------------------------------------------------------------
__global__ void transpose_w(const float* __restrict__ lw)
{
    int t = blockIdx.x * 256 + threadIdx.x;
    if (t < 25 * CDIM) {
        int ch = t / 25, tap = t - ch * 25;
        g_wt[tap * CDIM + ch] = lw[t];
    }
}

// ---------------------------------------------------------------------------
// Depthwise 5x5 conv (SAME, groups=C) over v -> g_lepe (+ bias)
// One thread per output element; ch fastest -> coalesced v & w loads.
// ---------------------------------------------------------------------------
__global__ __launch_bounds__(256) void dwconv(const float* __restrict__ lepe_b)
{
    int t = blockIdx.x * 256 + threadIdx.x;     // grid = 4608 blocks
    int ch = t & 255;
    int sp = t >> 8;                            // b*2304 + pos
    int b = sp / NPOS;
    int pos = sp - b * NPOS;
    int r = pos / GW, c = pos - (pos / GW) * GW;
    const float* vb = g_v + ((size_t)(b * HEADS + (ch >> 5)) * NPOS) * HD + (ch & 31);
    float sum = lepe_b[ch];
#pragma unroll
    for (int i = 0; i < 5; i++) {
        int rr = r + i - 2;
        if ((unsigned)rr < GW) {
#pragma unroll
            for (int j = 0; j < 5; j++) {
                int cc = c + j - 2;
                if ((unsigned)cc < GW) {
                    sum += vb[(size_t)(rr * GW + cc) * HD] * g_wt[(i * 5 + j) * CDIM + ch];
                }
            }
        }
    }
    g_lepe[t] = sum;
}

// ---------------------------------------------------------------------------
// Attention: one thread per query, flash-style over 64-key tiles.
// Logits are bounded (|qk| small, mask <= 0) so no running-max needed.
// grid = (18 q-tiles, 16 bh), 128 threads.
// ---------------------------------------------------------------------------
__global__ __launch_bounds__(128) void attn_kernel()
{
    __shared__ float ks[64 * HD];
    __shared__ float vs[64 * HD];

    const int bh = blockIdx.y;          // b*8 + h
    const int b = bh >> 3, h = bh & 7;
    const int qidx = blockIdx.x * 128 + threadIdx.x;

    const float* __restrict__ qbase = g_q + ((size_t)bh * NPOS + qidx) * HD;
    float4 q4[8];
#pragma unroll
    for (int i = 0; i < 8; i++) q4[i] = ((const float4*)qbase)[i];

    float4 a4[8];
#pragma unroll
    for (int i = 0; i < 8; i++) a4[i] = make_float4(0.f, 0.f, 0.f, 0.f);
    float l = 0.f;

    const int qr_ = qidx / GW;
    const int qc_ = qidx - qr_ * GW;
    const float decay = logf(1.0f - exp2f(-(1.0f + 0.375f * (float)h)));

    const float4* __restrict__ kglob = (const float4*)(g_k + (size_t)bh * NPOS * HD);
    const float4* __restrict__ vglob = (const float4*)(g_v + (size_t)bh * NPOS * HD);

    for (int t = 0; t < NPOS / 64; t++) {
        __syncthreads();
#pragma unroll
        for (int i = 0; i < 4; i++) {
            int idx = threadIdx.x + i * 128;                 // 0..511 float4s
            ((float4*)ks)[idx] = kglob[t * 512 + idx];
            ((float4*)vs)[idx] = vglob[t * 512 + idx];
        }
        __syncthreads();

        const int k0 = t * 64;
#pragma unroll 2
        for (int j = 0; j < 64; j++) {
            const float4* kj = (const float4*)(ks + j * HD);
            float d0 = 0.f, d1 = 0.f, d2 = 0.f, d3 = 0.f;
#pragma unroll
            for (int i = 0; i < 8; i += 4) {
                float4 kv0 = kj[i + 0];
                float4 kv1 = kj[i + 1];
                float4 kv2 = kj[i + 2];
                float4 kv3 = kj[i + 3];
                d0 += q4[i + 0].x * kv0.x + q4[i + 0].y * kv0.y + q4[i + 0].z * kv0.z + q4[i + 0].w * kv0.w;
                d1 += q4[i + 1].x * kv1.x + q4[i + 1].y * kv1.y + q4[i + 1].z * kv1.z + q4[i + 1].w * kv1.w;
                d2 += q4[i + 2].x * kv2.x + q4[i + 2].y * kv2.y + q4[i + 2].z * kv2.z + q4[i + 2].w * kv2.w;
                d3 += q4[i + 3].x * kv3.x + q4[i + 3].y * kv3.y + q4[i + 3].z * kv3.z + q4[i + 3].w * kv3.w;
            }
            float dot = (d0 + d1) + (d2 + d3);

            int kk = k0 + j;
            int kr_ = kk / GW;
            int kc_ = kk - kr_ * GW;
            float dist = (float)(abs(qr_ - kr_) + abs(qc_ - kc_));
            float p = __expf(dot + decay * dist);
            l += p;

            const float4* vj = (const float4*)(vs + j * HD);
#pragma unroll
            for (int i = 0; i < 8; i++) {
                float4 vv = vj[i];
                a4[i].x += p * vv.x;
                a4[i].y += p * vv.y;
                a4[i].z += p * vv.z;
                a4[i].w += p * vv.w;
            }
        }
    }

    const float inv = 1.0f / l;
    float* obase = g_attn + ((size_t)(b * NPOS + qidx)) * CDIM + h * HD;
#pragma unroll
    for (int i = 0; i < 8; i++) {
        float4 o = make_float4(a4[i].x * inv, a4[i].y * inv, a4[i].z * inv, a4[i].w * inv);
        ((float4*)obase)[i] = o;
    }
}

// ---------------------------------------------------------------------------
// Output GEMM: out = (g_attn + g_lepe) @ Wo + bo   [4608 x 256] x [256 x 256]
// ---------------------------------------------------------------------------
__global__ __launch_bounds__(256) void out_gemm(
    const float* __restrict__ Wo, const float* __restrict__ bo,
    float* __restrict__ out)
{
    __shared__ float As[16][64];
    __shared__ float Bs[16][64];

    const int tid = threadIdx.x;
    const int tx = tid & 15, ty = tid >> 4;
    const int mb = blockIdx.x * 64, nb = blockIdx.y * 64;

    float acc[4][4];
#pragma unroll
    for (int i = 0; i < 4; i++)
#pragma unroll
        for (int j = 0; j < 4; j++) acc[i][j] = 0.f;

    const int ar = tid >> 2, ac4 = (tid & 3) * 4;
    const int br = tid >> 4, bc4 = (tid & 15) * 4;

    for (int k0 = 0; k0 < CDIM; k0 += 16) {
        size_t aoff = (size_t)(mb + ar) * CDIM + k0 + ac4;
        float4 a1 = *(const float4*)&g_attn[aoff];
        float4 a2 = *(const float4*)&g_lepe[aoff];
        As[ac4 + 0][ar] = a1.x + a2.x; As[ac4 + 1][ar] = a1.y + a2.y;
        As[ac4 + 2][ar] = a1.z + a2.z; As[ac4 + 3][ar] = a1.w + a2.w;
        *(float4*)&Bs[br][bc4] = *(const float4*)&Wo[(size_t)(k0 + br) * CDIM + nb + bc4];
        __syncthreads();
#pragma unroll
        for (int kk = 0; kk < 16; kk++) {
            float4 av = *(float4*)&As[kk][ty * 4];
            float4 bv4 = *(float4*)&Bs[kk][tx * 4];
            acc[0][0] += av.x * bv4.x; acc[0][1] += av.x * bv4.y;
            acc[0][2] += av.x * bv4.z; acc[0][3] += av.x * bv4.w;
            acc[1][0] += av.y * bv4.x; acc[1][1] += av.y * bv4.y;
            acc[1][2] += av.y * bv4.z; acc[1][3] += av.y * bv4.w;
            acc[2][0] += av.z * bv4.x; acc[2][1] += av.z * bv4.y;
            acc[2][2] += av.z * bv4.z; acc[2][3] += av.z * bv4.w;
            acc[3][0] += av.w * bv4.x; acc[3][1] += av.w * bv4.y;
            acc[3][2] += av.w * bv4.z; acc[3][3] += av.w * bv4.w;
        }
        __syncthreads();
    }

#pragma unroll
    for (int i = 0; i < 4; i++) {
        int row = mb + ty * 4 + i;
#pragma unroll
        for (int j = 0; j < 4; j++) {
            int col = nb + tx * 4 + j;
            out[(size_t)row * CDIM + col] = acc[i][j] + bo[col];
        }
    }
}

// ---------------------------------------------------------------------------
extern "C" void kernel_launch(void* const* d_in, const int* in_sizes, int n_in,
                              void* d_out, int out_size)
{
    const float* x      = (const float*)d_in[0];
    const float* Wq     = (const float*)d_in[1];
    const float* bq     = (const float*)d_in[2];
    const float* Wk     = (const float*)d_in[3];
    const float* bk     = (const float*)d_in[4];
    const float* Wv     = (const float*)d_in[5];
    const float* bv     = (const float*)d_in[6];
    const float* lepe_w = (const float*)d_in[7];
    const float* lepe_b = (const float*)d_in[8];
    const float* Wo     = (const float*)d_in[9];
    const float* bo     = (const float*)d_in[10];
    float* out = (float*)d_out;

    dim3 g1(MTOT / 64, CDIM / 64, 3);
    qkv_gemm<<<g1, 256>>>(x, Wq, bq, Wk, bk, Wv, bv);

    transpose_w<<<(25 * CDIM + 255) / 256, 256>>>(lepe_w);

    dwconv<<<MTOT, 256>>>(lepe_b);

    dim3 g3(NPOS / 128, BATCH * HEADS);
    attn_kernel<<<g3, 128>>>();

    dim3 g4(MTOT / 64, CDIM / 64);
    out_gemm<<<g4, 256>>>(Wo, bo, out);
}